// round 1
// baseline (speedup 1.0000x reference)
#include <cuda_runtime.h>
#include <math.h>

#define BB 8
#define HH 512
#define WW 512
#define NPIX (BB*HH*WW)
#define INF_F 1.0e12f

// Scratch: intermediate 1D-EDT results (pass along W), one per mask.
__device__ float g_gt[NPIX];
__device__ float g_seg[NPIX];
// Accumulators: 0=hd_sum, 1=intersect, 2=sum(p1^2), 3=sum(lab), 4=ce_sum
__device__ double g_acc[5];

__global__ void init_acc_k() {
    int t = threadIdx.x;
    if (t < 5) g_acc[t] = 0.0;
}

// 1D binary EDT along a row held in shared memory: squared distance to nearest
// false element; INF_F if the whole row is true. Exact (integer-valued).
__device__ __forceinline__ float edt1d_bin(const unsigned char* m, int j) {
    if (!m[j]) return 0.0f;
    int lo = j, hi = WW - 1 - j;
    int rmax = (lo > hi) ? lo : hi;
    for (int r = 1; r <= rmax; r++) {
        bool found = false;
        if (r <= lo && !m[j - r]) found = true;
        if (r <= hi && !m[j + r]) found = true;
        if (found) return (float)(r * r);
    }
    return INF_F;
}

// Pass 1: per (batch,row). Computes row-wise 1D EDT for both masks and the
// pointwise CE/Dice partial sums.
__global__ void __launch_bounds__(512) pass1_k(const float* __restrict__ outputs,
                                               const int* __restrict__ label) {
    int row = blockIdx.x;
    int b   = blockIdx.y;
    int j   = threadIdx.x;

    __shared__ unsigned char mg[WW];
    __shared__ unsigned char ms[WW];

    size_t base1 = ((size_t)(b * 2 + 1) * HH + row) * WW;
    size_t base0 = ((size_t)(b * 2 + 0) * HH + row) * WW;
    float p1 = outputs[base1 + j];
    float p0 = outputs[base0 + j];
    int  lab = label[base1 + j];

    mg[j] = (lab > 0) ? 1 : 0;
    ms[j] = (p1 > 0.5f) ? 1 : 0;
    __syncthreads();

    size_t gidx = ((size_t)b * HH + row) * WW + j;
    g_gt[gidx]  = edt1d_bin(mg, j);
    g_seg[gidx] = edt1d_bin(ms, j);

    // Pointwise terms (CE over both channels, Dice over channel 1)
    float labf = (lab > 0) ? 1.0f : 0.0f;
    float mx   = fmaxf(p0, p1);
    float lse  = mx + logf(expf(p0 - mx) + expf(p1 - mx));
    float picked = (lab > 0) ? p1 : p0;

    double v0 = (double)(p1 * labf);     // intersect
    double v1 = (double)(p1 * p1);       // sum p1^2
    double v2 = (double)labf;            // sum lab (== lab^2)
    double v3 = (double)(lse - picked);  // ce term ( -picked summed )

    for (int off = 16; off > 0; off >>= 1) {
        v0 += __shfl_down_sync(0xFFFFFFFFu, v0, off);
        v1 += __shfl_down_sync(0xFFFFFFFFu, v1, off);
        v2 += __shfl_down_sync(0xFFFFFFFFu, v2, off);
        v3 += __shfl_down_sync(0xFFFFFFFFu, v3, off);
    }
    __shared__ double sb[16][4];
    int wid = j >> 5, lid = j & 31;
    if (lid == 0) { sb[wid][0] = v0; sb[wid][1] = v1; sb[wid][2] = v2; sb[wid][3] = v3; }
    __syncthreads();
    if (j < 4) {
        double s = 0.0;
        #pragma unroll
        for (int w = 0; w < 16; w++) s += sb[w][j];
        atomicAdd(&g_acc[1 + j], s);
    }
}

// Pass 2: column-direction EDT via exact windowed search, plus the HD loss
// reduction. Thread (i,j); consecutive j in a warp -> coalesced row reads.
__global__ void __launch_bounds__(1024) pass2_k(const float* __restrict__ outputs,
                                                const int* __restrict__ label) {
    int b = blockIdx.z;
    int i = blockIdx.y * blockDim.y + threadIdx.y;
    int j = blockIdx.x * blockDim.x + threadIdx.x;

    const float* gG = g_gt  + (size_t)b * HH * WW;
    const float* gS = g_seg + (size_t)b * HH * WW;

    float bestG = gG[i * WW + j];
    for (int r = 1; r < HH; r++) {
        float r2 = (float)(r * r);
        if (r2 >= bestG) break;   // no farther row can improve (g >= 0)
        if (i - r >= 0) bestG = fminf(bestG, gG[(i - r) * WW + j] + r2);
        if (i + r < HH) bestG = fminf(bestG, gG[(i + r) * WW + j] + r2);
    }
    float d2g = fminf(bestG, INF_F);

    float bestS = gS[i * WW + j];
    for (int r = 1; r < HH; r++) {
        float r2 = (float)(r * r);
        if (r2 >= bestS) break;
        if (i - r >= 0) bestS = fminf(bestS, gS[(i - r) * WW + j] + r2);
        if (i + r < HH) bestS = fminf(bestS, gS[(i + r) * WW + j] + r2);
    }
    float d2s = fminf(bestS, INF_F);

    size_t base1 = ((size_t)(b * 2 + 1) * HH + i) * WW + j;
    float p1   = outputs[base1];
    float labf = (label[base1] > 0) ? 1.0f : 0.0f;
    float dlt  = p1 - labf;
    double hd  = (double)(dlt * dlt) * ((double)d2s + (double)d2g);

    for (int off = 16; off > 0; off >>= 1)
        hd += __shfl_down_sync(0xFFFFFFFFu, hd, off);

    __shared__ double sb2[32];
    int tid = threadIdx.y * blockDim.x + threadIdx.x;
    int wid = tid >> 5, lid = tid & 31;
    if (lid == 0) sb2[wid] = hd;
    __syncthreads();
    if (wid == 0) {
        double s = sb2[lid];  // exactly 32 warps in a 1024-thread block
        for (int off = 16; off > 0; off >>= 1)
            s += __shfl_down_sync(0xFFFFFFFFu, s, off);
        if (lid == 0) atomicAdd(&g_acc[0], s);
    }
}

__global__ void finalize_k(float* out) {
    if (threadIdx.x == 0 && blockIdx.x == 0) {
        double N    = (double)NPIX;
        double hd   = g_acc[0] / N;
        double dice = 1.0 - (2.0 * g_acc[1] + 1e-6) / (g_acc[2] + g_acc[3] + 1e-6);
        double ce   = g_acc[4] / N;
        // LAM = 1.0, ALPHA = 0.5 -> loss = (ce + dice) + 0.5 * hd
        out[0] = (float)((ce + dice) + 0.5 * hd);
    }
}

extern "C" void kernel_launch(void* const* d_in, const int* in_sizes, int n_in,
                              void* d_out, int out_size) {
    const float* outputs = (const float*)d_in[0];
    const int*   label   = (const int*)d_in[1];
    float*       out     = (float*)d_out;

    init_acc_k<<<1, 32>>>();

    dim3 g1(HH, BB);
    pass1_k<<<g1, WW>>>(outputs, label);

    dim3 b2(128, 8);
    dim3 g2(WW / 128, HH / 8, BB);
    pass2_k<<<g2, b2>>>(outputs, label);

    finalize_k<<<1, 32>>>(out);
}

// round 2
// speedup vs baseline: 2.6646x; 2.6646x over previous
#include <cuda_runtime.h>
#include <math.h>

#define BB 8
#define HH 512
#define WW 512
#define NPIX (BB*HH*WW)
#define INF_F 1.0e12f

#define NBLK1 (BB*HH)            // 4096 pass1 blocks
#define NBLK2 ((WW/128)*(HH/8)*BB)  // 2048 pass2 blocks

// Scratch: intermediate 1D-EDT results (pass along W), one per mask.
__device__ float g_gt[NPIX];
__device__ float g_seg[NPIX];
// Per-block partial sums (no atomics): pass1 -> [bid][0..3] =
// {intersect, sum p1^2, sum lab, ce}; pass2 -> g_hd[bid] = hd partial.
__device__ double g_part[NBLK1 * 4];
__device__ double g_hd[NBLK2];

// 1D binary EDT along a row held in shared memory: squared distance to nearest
// false element; INF_F if the whole row is true. Exact (integer-valued).
__device__ __forceinline__ float edt1d_bin(const unsigned char* m, int j) {
    if (!m[j]) return 0.0f;
    int lo = j, hi = WW - 1 - j;
    int rmax = (lo > hi) ? lo : hi;
    for (int r = 1; r <= rmax; r++) {
        bool found = false;
        if (r <= lo && !m[j - r]) found = true;
        if (r <= hi && !m[j + r]) found = true;
        if (found) return (float)(r * r);
    }
    return INF_F;
}

// Pass 1: per (batch,row). Row-wise 1D EDT for both masks + pointwise CE/Dice
// partial sums (warp reduce in fp32, block accumulate in fp64, NO atomics).
__global__ void __launch_bounds__(512) pass1_k(const float* __restrict__ outputs,
                                               const int* __restrict__ label) {
    int row = blockIdx.x;
    int b   = blockIdx.y;
    int j   = threadIdx.x;

    __shared__ unsigned char mg[WW];
    __shared__ unsigned char ms[WW];

    size_t base1 = ((size_t)(b * 2 + 1) * HH + row) * WW;
    size_t base0 = ((size_t)(b * 2 + 0) * HH + row) * WW;
    float p1 = outputs[base1 + j];
    float p0 = outputs[base0 + j];
    int  lab = label[base1 + j];

    mg[j] = (lab > 0) ? 1 : 0;
    ms[j] = (p1 > 0.5f) ? 1 : 0;
    __syncthreads();

    size_t gidx = ((size_t)b * HH + row) * WW + j;
    g_gt[gidx]  = edt1d_bin(mg, j);
    g_seg[gidx] = edt1d_bin(ms, j);

    // Pointwise terms
    float labf = (lab > 0) ? 1.0f : 0.0f;
    float mx   = fmaxf(p0, p1);
    float lse  = mx + logf(expf(p0 - mx) + expf(p1 - mx));
    float picked = (lab > 0) ? p1 : p0;

    float v0 = p1 * labf;      // intersect
    float v1 = p1 * p1;        // sum p1^2
    float v2 = labf;           // sum lab (== lab^2)
    float v3 = lse - picked;   // ce term

    #pragma unroll
    for (int off = 16; off > 0; off >>= 1) {
        v0 += __shfl_down_sync(0xFFFFFFFFu, v0, off);
        v1 += __shfl_down_sync(0xFFFFFFFFu, v1, off);
        v2 += __shfl_down_sync(0xFFFFFFFFu, v2, off);
        v3 += __shfl_down_sync(0xFFFFFFFFu, v3, off);
    }
    __shared__ float sb[16][4];
    int wid = j >> 5, lid = j & 31;
    if (lid == 0) { sb[wid][0] = v0; sb[wid][1] = v1; sb[wid][2] = v2; sb[wid][3] = v3; }
    __syncthreads();
    if (j < 4) {
        double s = 0.0;
        #pragma unroll
        for (int w = 0; w < 16; w++) s += (double)sb[w][j];
        int bid = b * HH + row;
        g_part[bid * 4 + j] = s;
    }
}

// Pass 2: column-direction EDT via exact windowed search (both masks
// interleaved for MLP), plus the HD partial sum (no atomics).
__global__ void __launch_bounds__(1024) pass2_k(const float* __restrict__ outputs,
                                                const int* __restrict__ label) {
    int b = blockIdx.z;
    int i = blockIdx.y * blockDim.y + threadIdx.y;
    int j = blockIdx.x * blockDim.x + threadIdx.x;

    const float* gG = g_gt  + (size_t)b * HH * WW;
    const float* gS = g_seg + (size_t)b * HH * WW;

    float bestG = gG[i * WW + j];
    float bestS = gS[i * WW + j];

    for (int r = 1; r < HH; r++) {
        float r2 = (float)(r * r);
        bool cg = r2 < bestG;
        bool cs = r2 < bestS;
        if (!cg && !cs) break;
        bool up = (i - r >= 0), dn = (i + r < HH);
        if (cg) {
            if (up) bestG = fminf(bestG, gG[(i - r) * WW + j] + r2);
            if (dn) bestG = fminf(bestG, gG[(i + r) * WW + j] + r2);
        }
        if (cs) {
            if (up) bestS = fminf(bestS, gS[(i - r) * WW + j] + r2);
            if (dn) bestS = fminf(bestS, gS[(i + r) * WW + j] + r2);
        }
    }
    float d2g = fminf(bestG, INF_F);
    float d2s = fminf(bestS, INF_F);

    size_t base1 = ((size_t)(b * 2 + 1) * HH + i) * WW + j;
    float p1   = outputs[base1];
    float labf = (label[base1] > 0) ? 1.0f : 0.0f;
    float dlt  = p1 - labf;
    float hd   = (dlt * dlt) * (d2s + d2g);

    #pragma unroll
    for (int off = 16; off > 0; off >>= 1)
        hd += __shfl_down_sync(0xFFFFFFFFu, hd, off);

    __shared__ double sb2[32];
    int tid = threadIdx.y * blockDim.x + threadIdx.x;
    int wid = tid >> 5, lid = tid & 31;
    if (lid == 0) sb2[wid] = (double)hd;
    __syncthreads();
    if (wid == 0) {
        double s = sb2[lid];  // exactly 32 warps per 1024-thread block
        #pragma unroll
        for (int off = 16; off > 0; off >>= 1)
            s += __shfl_down_sync(0xFFFFFFFFu, s, off);
        if (lid == 0) {
            int bid = (blockIdx.z * gridDim.y + blockIdx.y) * gridDim.x + blockIdx.x;
            g_hd[bid] = s;
        }
    }
}

// Final reduce of all per-block partials + scalar epilogue. One 512-thread block.
__global__ void __launch_bounds__(512) finalize_k(float* out) {
    int t = threadIdx.x;
    double s0 = 0.0, s1 = 0.0, s2 = 0.0, s3 = 0.0, sh = 0.0;
    for (int bIdx = t; bIdx < NBLK1; bIdx += 512) {
        s0 += g_part[bIdx * 4 + 0];
        s1 += g_part[bIdx * 4 + 1];
        s2 += g_part[bIdx * 4 + 2];
        s3 += g_part[bIdx * 4 + 3];
    }
    for (int bIdx = t; bIdx < NBLK2; bIdx += 512) sh += g_hd[bIdx];

    #pragma unroll
    for (int off = 16; off > 0; off >>= 1) {
        s0 += __shfl_down_sync(0xFFFFFFFFu, s0, off);
        s1 += __shfl_down_sync(0xFFFFFFFFu, s1, off);
        s2 += __shfl_down_sync(0xFFFFFFFFu, s2, off);
        s3 += __shfl_down_sync(0xFFFFFFFFu, s3, off);
        sh += __shfl_down_sync(0xFFFFFFFFu, sh, off);
    }
    __shared__ double sb[16][5];
    int wid = t >> 5, lid = t & 31;
    if (lid == 0) { sb[wid][0]=s0; sb[wid][1]=s1; sb[wid][2]=s2; sb[wid][3]=s3; sb[wid][4]=sh; }
    __syncthreads();
    if (t == 0) {
        double a0=0, a1=0, a2=0, a3=0, ah=0;
        #pragma unroll
        for (int w = 0; w < 16; w++) {
            a0 += sb[w][0]; a1 += sb[w][1]; a2 += sb[w][2]; a3 += sb[w][3]; ah += sb[w][4];
        }
        double N    = (double)NPIX;
        double hd   = ah / N;
        double dice = 1.0 - (2.0 * a0 + 1e-6) / (a1 + a2 + 1e-6);
        double ce   = a3 / N;
        // LAM = 1.0, ALPHA = 0.5 -> loss = (ce + dice) + 0.5 * hd
        out[0] = (float)((ce + dice) + 0.5 * hd);
    }
}

extern "C" void kernel_launch(void* const* d_in, const int* in_sizes, int n_in,
                              void* d_out, int out_size) {
    const float* outputs = (const float*)d_in[0];
    const int*   label   = (const int*)d_in[1];
    float*       out     = (float*)d_out;

    dim3 g1(HH, BB);
    pass1_k<<<g1, WW>>>(outputs, label);

    dim3 b2(128, 8);
    dim3 g2(WW / 128, HH / 8, BB);
    pass2_k<<<g2, b2>>>(outputs, label);

    finalize_k<<<1, 512>>>(out);
}

// round 3
// speedup vs baseline: 2.6676x; 1.0011x over previous
#include <cuda_runtime.h>
#include <math.h>

#define BB 8
#define HH 512
#define WW 512
#define NPIX (BB*HH*WW)
#define INF_F 1.0e12f

#define NBLK1 (BB*HH)         // 4096 pass1 blocks (one per row)
#define NBLK2 (4*128*8)       // 4096 pass2 blocks

// Scratch: intermediate 1D-EDT results (pass along W), one per mask.
__device__ float g_gt[NPIX];
__device__ float g_seg[NPIX];
// Per-block partial sums (no hot atomics): pass1 -> [bid][0..3] =
// {intersect, sum p1^2, sum lab, ce}; pass2 -> g_hd[bid].
__device__ double g_part[NBLK1 * 4];
__device__ double g_hd[NBLK2];
__device__ unsigned g_count;   // zero-init at load; last block resets it

// Nearest-zero-bit squared distance in a 512-bit row stored as 16 uint32
// words where set bit == background (zero/foreground inverted already).
__device__ __forceinline__ float nz_d2(const unsigned* __restrict__ z, int j) {
    int w  = j >> 5;
    int jb = j & 31;
    const int BIG = 1 << 20;
    // left: set bits at positions <= jb in own word
    int dl = BIG;
    unsigned t = z[w] & (0xFFFFFFFFu >> (31 - jb));
    if (t) {
        dl = jb - (31 - __clz(t));
    } else {
        #pragma unroll 4
        for (int ww = w - 1; ww >= 0; --ww) {
            unsigned zz = z[ww];
            if (zz) { dl = j - (ww * 32 + 31 - __clz(zz)); break; }
        }
    }
    // right: set bits at positions >= jb in own word
    int dr = BIG;
    unsigned u = z[w] & (0xFFFFFFFFu << jb);
    if (u) {
        dr = (__ffs(u) - 1) - jb;
    } else {
        #pragma unroll 4
        for (int ww = w + 1; ww < 16; ++ww) {
            unsigned zz = z[ww];
            if (zz) { dr = ww * 32 + (__ffs(zz) - 1) - j; break; }
        }
    }
    int d = min(dl, dr);
    if (d >= BIG) return INF_F;          // whole row is foreground
    return (float)(d * d);
}

// Pass 1: per (batch,row). Row-wise 1D EDT for both masks via ballot bitmasks
// + pointwise CE/Dice partial sums (warp fp32, block fp64, no atomics).
__global__ void __launch_bounds__(512) pass1_k(const float* __restrict__ outputs,
                                               const int* __restrict__ label) {
    int row = blockIdx.x;
    int b   = blockIdx.y;
    int j   = threadIdx.x;
    int wid = j >> 5, lid = j & 31;

    __shared__ unsigned zg[16];   // set bit == (lab == 0)
    __shared__ unsigned zs[16];   // set bit == (p1 <= 0.5)

    size_t base1 = ((size_t)(b * 2 + 1) * HH + row) * WW;
    size_t base0 = ((size_t)(b * 2 + 0) * HH + row) * WW;
    float p1 = outputs[base1 + j];
    float p0 = outputs[base0 + j];
    int  lab = label[base1 + j];

    unsigned bg = __ballot_sync(0xFFFFFFFFu, lab > 0);
    unsigned bs = __ballot_sync(0xFFFFFFFFu, p1 > 0.5f);
    if (lid == 0) { zg[wid] = ~bg; zs[wid] = ~bs; }
    __syncthreads();

    size_t gidx = ((size_t)b * HH + row) * WW + j;
    g_gt[gidx]  = nz_d2(zg, j);
    g_seg[gidx] = nz_d2(zs, j);

    // Pointwise terms (fast-math CE; rel err ~1e-6, budget is 1e-3)
    float labf = (lab > 0) ? 1.0f : 0.0f;
    float mx   = fmaxf(p0, p1);
    float lse  = mx + __logf(__expf(p0 - mx) + __expf(p1 - mx));
    float picked = (lab > 0) ? p1 : p0;

    float v0 = p1 * labf;      // intersect
    float v1 = p1 * p1;        // sum p1^2
    float v2 = labf;           // sum lab (== lab^2)
    float v3 = lse - picked;   // ce term

    #pragma unroll
    for (int off = 16; off > 0; off >>= 1) {
        v0 += __shfl_down_sync(0xFFFFFFFFu, v0, off);
        v1 += __shfl_down_sync(0xFFFFFFFFu, v1, off);
        v2 += __shfl_down_sync(0xFFFFFFFFu, v2, off);
        v3 += __shfl_down_sync(0xFFFFFFFFu, v3, off);
    }
    __shared__ float sb[16][4];
    if (lid == 0) { sb[wid][0] = v0; sb[wid][1] = v1; sb[wid][2] = v2; sb[wid][3] = v3; }
    __syncthreads();
    if (j < 4) {
        double s = 0.0;
        #pragma unroll
        for (int w = 0; w < 16; w++) s += (double)sb[w][j];
        g_part[(b * HH + row) * 4 + j] = s;
    }
}

// Pass 2: column-direction EDT via exact windowed search (both masks
// interleaved for MLP), HD partial sum, and last-block finalize.
__global__ void __launch_bounds__(512) pass2_k(const float* __restrict__ outputs,
                                               const int* __restrict__ label,
                                               float* __restrict__ out) {
    int b = blockIdx.z;
    int i = blockIdx.y * blockDim.y + threadIdx.y;
    int j = blockIdx.x * blockDim.x + threadIdx.x;

    const float* gG = g_gt  + (size_t)b * HH * WW;
    const float* gS = g_seg + (size_t)b * HH * WW;

    float bestG = gG[i * WW + j];
    float bestS = gS[i * WW + j];

    for (int r = 1; r < HH; r++) {
        float r2 = (float)(r * r);
        bool cg = r2 < bestG;
        bool cs = r2 < bestS;
        if (!cg && !cs) break;
        bool up = (i - r >= 0), dn = (i + r < HH);
        if (cg) {
            if (up) bestG = fminf(bestG, gG[(i - r) * WW + j] + r2);
            if (dn) bestG = fminf(bestG, gG[(i + r) * WW + j] + r2);
        }
        if (cs) {
            if (up) bestS = fminf(bestS, gS[(i - r) * WW + j] + r2);
            if (dn) bestS = fminf(bestS, gS[(i + r) * WW + j] + r2);
        }
    }
    float d2g = fminf(bestG, INF_F);
    float d2s = fminf(bestS, INF_F);

    size_t base1 = ((size_t)(b * 2 + 1) * HH + i) * WW + j;
    float p1   = outputs[base1];
    float labf = (label[base1] > 0) ? 1.0f : 0.0f;
    float dlt  = p1 - labf;
    float hd   = (dlt * dlt) * (d2s + d2g);

    #pragma unroll
    for (int off = 16; off > 0; off >>= 1)
        hd += __shfl_down_sync(0xFFFFFFFFu, hd, off);

    __shared__ double sbh[16];
    int tid = threadIdx.y * blockDim.x + threadIdx.x;
    int wid = tid >> 5, lid = tid & 31;
    if (lid == 0) sbh[wid] = (double)hd;
    __syncthreads();

    int bid = (blockIdx.z * gridDim.y + blockIdx.y) * gridDim.x + blockIdx.x;
    if (tid < 16) {
        // reduce the 16 warp partials with a mini shuffle tree in warp 0
        double s = sbh[tid];
        #pragma unroll
        for (int off = 8; off > 0; off >>= 1)
            s += __shfl_down_sync(0x0000FFFFu, s, off);
        if (tid == 0) g_hd[bid] = s;
    }

    // ── last-block finalize ──
    __shared__ bool isLast;
    if (tid == 0) {
        __threadfence();
        unsigned c = atomicAdd(&g_count, 1u);
        isLast = (c == NBLK2 - 1);
    }
    __syncthreads();
    if (!isLast) return;
    __threadfence();

    double s0 = 0.0, s1 = 0.0, s2 = 0.0, s3 = 0.0, sh = 0.0;
    for (int k = tid; k < NBLK1; k += 512) {
        s0 += g_part[k * 4 + 0];
        s1 += g_part[k * 4 + 1];
        s2 += g_part[k * 4 + 2];
        s3 += g_part[k * 4 + 3];
    }
    for (int k = tid; k < NBLK2; k += 512) sh += g_hd[k];

    #pragma unroll
    for (int off = 16; off > 0; off >>= 1) {
        s0 += __shfl_down_sync(0xFFFFFFFFu, s0, off);
        s1 += __shfl_down_sync(0xFFFFFFFFu, s1, off);
        s2 += __shfl_down_sync(0xFFFFFFFFu, s2, off);
        s3 += __shfl_down_sync(0xFFFFFFFFu, s3, off);
        sh += __shfl_down_sync(0xFFFFFFFFu, sh, off);
    }
    __shared__ double fb[16][5];
    if (lid == 0) { fb[wid][0]=s0; fb[wid][1]=s1; fb[wid][2]=s2; fb[wid][3]=s3; fb[wid][4]=sh; }
    __syncthreads();
    if (tid == 0) {
        double a0=0, a1=0, a2=0, a3=0, ah=0;
        #pragma unroll
        for (int w = 0; w < 16; w++) {
            a0 += fb[w][0]; a1 += fb[w][1]; a2 += fb[w][2]; a3 += fb[w][3]; ah += fb[w][4];
        }
        double N    = (double)NPIX;
        double hd   = ah / N;
        double dice = 1.0 - (2.0 * a0 + 1e-6) / (a1 + a2 + 1e-6);
        double ce   = a3 / N;
        // LAM = 1.0, ALPHA = 0.5 -> loss = (ce + dice) + 0.5 * hd
        out[0] = (float)((ce + dice) + 0.5 * hd);
        g_count = 0;   // reset for next graph replay
    }
}

extern "C" void kernel_launch(void* const* d_in, const int* in_sizes, int n_in,
                              void* d_out, int out_size) {
    const float* outputs = (const float*)d_in[0];
    const int*   label   = (const int*)d_in[1];
    float*       out     = (float*)d_out;

    dim3 g1(HH, BB);
    pass1_k<<<g1, WW>>>(outputs, label);

    dim3 b2(128, 4);
    dim3 g2(WW / 128, HH / 4, BB);
    pass2_k<<<g2, b2>>>(outputs, label, out);
}

// round 4
// speedup vs baseline: 2.7655x; 1.0367x over previous
#include <cuda_runtime.h>
#include <math.h>

#define BB 8
#define HH 512
#define WW 512
#define NPIX (BB*HH*WW)
#define INF_F 1.0e12f

#define NBLK1 (BB*HH)         // 4096 pass1 blocks (one per row)
#define NBLK2 (4*128*8)       // 4096 pass2 blocks
#define DSENT 30000           // sentinel distance: DSENT^2 = 9e8 (int32-safe)
#define SENT2 900000000

// Packed row-EDT distances: lo16 = gt distance, hi16 = seg distance (linear
// distance, not squared; DSENT if the whole row is foreground).
__device__ unsigned g_pack[NPIX];
// Per-block partial sums (no hot atomics): pass1 -> [bid][0..3] =
// {intersect, sum p1^2, sum lab, ce}; pass2 -> g_hd[bid].
__device__ double g_part[NBLK1 * 4];
__device__ double g_hd[NBLK2];
__device__ unsigned g_count;   // zero-init at load; last block resets it

// Nearest-set-bit distance in a 512-bit row stored as 16 uint32 words
// (set bit == background). Returns linear distance, DSENT if none.
__device__ __forceinline__ int nz_d(const unsigned* __restrict__ z, int j) {
    int w  = j >> 5;
    int jb = j & 31;
    int dl = DSENT;
    unsigned t = z[w] & (0xFFFFFFFFu >> (31 - jb));
    if (t) {
        dl = jb - (31 - __clz(t));
    } else {
        #pragma unroll 4
        for (int ww = w - 1; ww >= 0; --ww) {
            unsigned zz = z[ww];
            if (zz) { dl = j - (ww * 32 + 31 - __clz(zz)); break; }
        }
    }
    int dr = DSENT;
    unsigned u = z[w] & (0xFFFFFFFFu << jb);
    if (u) {
        dr = (__ffs(u) - 1) - jb;
    } else {
        #pragma unroll 4
        for (int ww = w + 1; ww < 16; ++ww) {
            unsigned zz = z[ww];
            if (zz) { dr = ww * 32 + (__ffs(zz) - 1) - j; break; }
        }
    }
    return min(dl, dr);
}

// Pass 1: per (batch,row). Row-wise 1D EDT for both masks via ballot bitmasks
// (packed u32 store) + pointwise CE/Dice partial sums.
__global__ void __launch_bounds__(512) pass1_k(const float* __restrict__ outputs,
                                               const int* __restrict__ label) {
    int row = blockIdx.x;
    int b   = blockIdx.y;
    int j   = threadIdx.x;
    int wid = j >> 5, lid = j & 31;

    __shared__ unsigned zg[16];   // set bit == (lab == 0)
    __shared__ unsigned zs[16];   // set bit == (p1 <= 0.5)

    size_t base1 = ((size_t)(b * 2 + 1) * HH + row) * WW;
    size_t base0 = ((size_t)(b * 2 + 0) * HH + row) * WW;
    float p1 = outputs[base1 + j];
    float p0 = outputs[base0 + j];
    int  lab = label[base1 + j];

    unsigned bg = __ballot_sync(0xFFFFFFFFu, lab > 0);
    unsigned bs = __ballot_sync(0xFFFFFFFFu, p1 > 0.5f);
    if (lid == 0) { zg[wid] = ~bg; zs[wid] = ~bs; }
    __syncthreads();

    int dg = nz_d(zg, j);
    int ds = nz_d(zs, j);
    g_pack[((size_t)b * HH + row) * WW + j] = (unsigned)dg | ((unsigned)ds << 16);

    // Pointwise terms (fast-math CE; rel err ~1e-6, budget is 1e-3)
    float labf = (lab > 0) ? 1.0f : 0.0f;
    float mx   = fmaxf(p0, p1);
    float lse  = mx + __logf(__expf(p0 - mx) + __expf(p1 - mx));
    float picked = (lab > 0) ? p1 : p0;

    float v0 = p1 * labf;      // intersect
    float v1 = p1 * p1;        // sum p1^2
    float v2 = labf;           // sum lab (== lab^2)
    float v3 = lse - picked;   // ce term

    #pragma unroll
    for (int off = 16; off > 0; off >>= 1) {
        v0 += __shfl_down_sync(0xFFFFFFFFu, v0, off);
        v1 += __shfl_down_sync(0xFFFFFFFFu, v1, off);
        v2 += __shfl_down_sync(0xFFFFFFFFu, v2, off);
        v3 += __shfl_down_sync(0xFFFFFFFFu, v3, off);
    }
    __shared__ float sb[16][4];
    if (lid == 0) { sb[wid][0] = v0; sb[wid][1] = v1; sb[wid][2] = v2; sb[wid][3] = v3; }
    __syncthreads();
    if (j < 4) {
        double s = 0.0;
        #pragma unroll
        for (int w = 0; w < 16; w++) s += (double)sb[w][j];
        g_part[(b * HH + row) * 4 + j] = s;
    }
}

// Pass 2: column-direction EDT. Batched r=1..4 window (8 independent packed
// loads, MLP=8) + rare serial tail; HD partial sum; last-block finalize.
__global__ void __launch_bounds__(512) pass2_k(const float* __restrict__ outputs,
                                               const int* __restrict__ label,
                                               float* __restrict__ out) {
    int b = blockIdx.z;
    int i = blockIdx.y * blockDim.y + threadIdx.y;
    int j = blockIdx.x * blockDim.x + threadIdx.x;

    const unsigned* __restrict__ P = g_pack + (size_t)b * HH * WW;

    unsigned c = P[i * WW + j];
    int dg = (int)(c & 0xFFFFu);
    int ds = (int)(c >> 16);
    int bestG = dg * dg;
    int bestS = ds * ds;

    // Unconditional batched window: clamped indices give candidates that are
    // always >= an already-considered candidate, so exactness is preserved.
    #pragma unroll
    for (int r = 1; r <= 4; r++) {
        int iu = max(i - r, 0);
        int id = min(i + r, HH - 1);
        unsigned cu = P[iu * WW + j];
        unsigned cd = P[id * WW + j];
        int r2 = r * r;
        int gu = (int)(cu & 0xFFFFu); gu = gu * gu + r2;
        int su = (int)(cu >> 16);     su = su * su + r2;
        int gd = (int)(cd & 0xFFFFu); gd = gd * gd + r2;
        int sd = (int)(cd >> 16);     sd = sd * sd + r2;
        bestG = min(bestG, min(gu, gd));
        bestS = min(bestS, min(su, sd));
    }

    // Rare tail (best still > 16 after radius-4 window)
    if (bestG > 16 || bestS > 16) {
        for (int r = 5; r < HH; r++) {
            int r2 = r * r;
            bool cg = r2 < bestG;
            bool cs = r2 < bestS;
            if (!cg && !cs) break;
            if (i - r >= 0) {
                unsigned cc = P[(i - r) * WW + j];
                int vg = (int)(cc & 0xFFFFu);
                int vs = (int)(cc >> 16);
                bestG = min(bestG, vg * vg + r2);
                bestS = min(bestS, vs * vs + r2);
            }
            if (i + r < HH) {
                unsigned cc = P[(i + r) * WW + j];
                int vg = (int)(cc & 0xFFFFu);
                int vs = (int)(cc >> 16);
                bestG = min(bestG, vg * vg + r2);
                bestS = min(bestS, vs * vs + r2);
            }
        }
    }

    float d2g = (bestG >= SENT2) ? INF_F : (float)bestG;
    float d2s = (bestS >= SENT2) ? INF_F : (float)bestS;

    size_t base1 = ((size_t)(b * 2 + 1) * HH + i) * WW + j;
    float p1   = outputs[base1];
    float labf = (label[base1] > 0) ? 1.0f : 0.0f;
    float dlt  = p1 - labf;
    float hd   = (dlt * dlt) * (d2s + d2g);

    #pragma unroll
    for (int off = 16; off > 0; off >>= 1)
        hd += __shfl_down_sync(0xFFFFFFFFu, hd, off);

    __shared__ double sbh[16];
    int tid = threadIdx.y * blockDim.x + threadIdx.x;
    int wid = tid >> 5, lid = tid & 31;
    if (lid == 0) sbh[wid] = (double)hd;
    __syncthreads();

    int bid = (blockIdx.z * gridDim.y + blockIdx.y) * gridDim.x + blockIdx.x;
    if (tid < 16) {
        double s = sbh[tid];
        #pragma unroll
        for (int off = 8; off > 0; off >>= 1)
            s += __shfl_down_sync(0x0000FFFFu, s, off);
        if (tid == 0) g_hd[bid] = s;
    }

    // ── last-block finalize ──
    __shared__ bool isLast;
    if (tid == 0) {
        __threadfence();
        unsigned cnum = atomicAdd(&g_count, 1u);
        isLast = (cnum == NBLK2 - 1);
    }
    __syncthreads();
    if (!isLast) return;
    __threadfence();

    double s0 = 0.0, s1 = 0.0, s2 = 0.0, s3 = 0.0, sh = 0.0;
    for (int k = tid; k < NBLK1; k += 512) {
        s0 += g_part[k * 4 + 0];
        s1 += g_part[k * 4 + 1];
        s2 += g_part[k * 4 + 2];
        s3 += g_part[k * 4 + 3];
    }
    for (int k = tid; k < NBLK2; k += 512) sh += g_hd[k];

    #pragma unroll
    for (int off = 16; off > 0; off >>= 1) {
        s0 += __shfl_down_sync(0xFFFFFFFFu, s0, off);
        s1 += __shfl_down_sync(0xFFFFFFFFu, s1, off);
        s2 += __shfl_down_sync(0xFFFFFFFFu, s2, off);
        s3 += __shfl_down_sync(0xFFFFFFFFu, s3, off);
        sh += __shfl_down_sync(0xFFFFFFFFu, sh, off);
    }
    __shared__ double fb[16][5];
    if (lid == 0) { fb[wid][0]=s0; fb[wid][1]=s1; fb[wid][2]=s2; fb[wid][3]=s3; fb[wid][4]=sh; }
    __syncthreads();
    if (tid == 0) {
        double a0=0, a1=0, a2=0, a3=0, ah=0;
        #pragma unroll
        for (int w = 0; w < 16; w++) {
            a0 += fb[w][0]; a1 += fb[w][1]; a2 += fb[w][2]; a3 += fb[w][3]; ah += fb[w][4];
        }
        double N    = (double)NPIX;
        double hd   = ah / N;
        double dice = 1.0 - (2.0 * a0 + 1e-6) / (a1 + a2 + 1e-6);
        double ce   = a3 / N;
        // LAM = 1.0, ALPHA = 0.5 -> loss = (ce + dice) + 0.5 * hd
        out[0] = (float)((ce + dice) + 0.5 * hd);
        g_count = 0;   // reset for next graph replay
    }
}

extern "C" void kernel_launch(void* const* d_in, const int* in_sizes, int n_in,
                              void* d_out, int out_size) {
    const float* outputs = (const float*)d_in[0];
    const int*   label   = (const int*)d_in[1];
    float*       out     = (float*)d_out;

    dim3 g1(HH, BB);
    pass1_k<<<g1, WW>>>(outputs, label);

    dim3 b2(128, 4);
    dim3 g2(WW / 128, HH / 4, BB);
    pass2_k<<<g2, b2>>>(outputs, label, out);
}

// round 5
// speedup vs baseline: 4.3687x; 1.5797x over previous
#include <cuda_runtime.h>
#include <math.h>

#define BB 8
#define HH 512
#define WW 512
#define NPIX (BB*HH*WW)
#define INF_F 1.0e12f

#define NBLK1 (BB*HH)         // 4096 pass1 blocks (one per row)
#define NBLK2 (4*32*8)        // 1024 pass2 blocks (128x16 tiles)
#define DSENT 30000           // sentinel distance: DSENT^2 = 9e8 (int32-safe)
#define SENT2 900000000

// Packed row-EDT distances: lo16 = gt distance, hi16 = seg distance (linear).
__device__ unsigned g_pack[NPIX];
// Per-block partial sums (no hot atomics).
__device__ double g_part[NBLK1 * 4];
__device__ double g_hd[NBLK2];
__device__ unsigned g_count;   // zero-init at load; last block resets it

// Nearest-set-bit distance in a 512-bit row stored as 16 uint32 words
// (set bit == background). Returns linear distance, DSENT if none.
__device__ __forceinline__ int nz_d(const unsigned* __restrict__ z, int j) {
    int w  = j >> 5;
    int jb = j & 31;
    int dl = DSENT;
    unsigned t = z[w] & (0xFFFFFFFFu >> (31 - jb));
    if (t) {
        dl = jb - (31 - __clz(t));
    } else {
        #pragma unroll 4
        for (int ww = w - 1; ww >= 0; --ww) {
            unsigned zz = z[ww];
            if (zz) { dl = j - (ww * 32 + 31 - __clz(zz)); break; }
        }
    }
    int dr = DSENT;
    unsigned u = z[w] & (0xFFFFFFFFu << jb);
    if (u) {
        dr = (__ffs(u) - 1) - jb;
    } else {
        #pragma unroll 4
        for (int ww = w + 1; ww < 16; ++ww) {
            unsigned zz = z[ww];
            if (zz) { dr = ww * 32 + (__ffs(zz) - 1) - j; break; }
        }
    }
    return min(dl, dr);
}

// Pack per-thread 4-bit nibbles into 32-bit row-mask words.
// Lane l holds bits for pixels 4l..4l+3; after 3 shuffle steps lanes
// {0,8,16,24} hold words {0,1,2,3} of this warp's 128-pixel span.
__device__ __forceinline__ unsigned pack_nibbles(unsigned nib) {
    unsigned v = nib | (__shfl_xor_sync(0xFFFFFFFFu, nib, 1) << 4);
    v = v | (__shfl_xor_sync(0xFFFFFFFFu, v, 2) << 8);
    v = v | (__shfl_xor_sync(0xFFFFFFFFu, v, 4) << 16);
    return v;   // valid at lanes == 0 (mod 8)
}

// Pass 1: 128 threads per (batch,row), 4 pixels each, vectorized loads.
__global__ void __launch_bounds__(128) pass1_k(const float* __restrict__ outputs,
                                               const int* __restrict__ label) {
    int row = blockIdx.x;
    int b   = blockIdx.y;
    int t   = threadIdx.x;
    int wid = t >> 5, lid = t & 31;
    int j4  = t * 4;

    __shared__ unsigned zg[16];   // set bit == (lab == 0)
    __shared__ unsigned zs[16];   // set bit == (p1 <= 0.5)

    size_t base1 = ((size_t)(b * 2 + 1) * HH + row) * WW;
    size_t base0 = ((size_t)(b * 2 + 0) * HH + row) * WW;
    float4 p1v = *(const float4*)(outputs + base1 + j4);
    float4 p0v = *(const float4*)(outputs + base0 + j4);
    int4   lbv = *(const int4*)(label + base1 + j4);

    float p1a[4] = {p1v.x, p1v.y, p1v.z, p1v.w};
    float p0a[4] = {p0v.x, p0v.y, p0v.z, p0v.w};
    int   lba[4] = {lbv.x, lbv.y, lbv.z, lbv.w};

    unsigned nibg = 0, nibs = 0;
    #pragma unroll
    for (int k = 0; k < 4; k++) {
        nibg |= (lba[k] > 0 ? 0u : 1u) << k;       // set bit == background
        nibs |= (p1a[k] > 0.5f ? 0u : 1u) << k;
    }
    unsigned wg = pack_nibbles(nibg);
    unsigned ws = pack_nibbles(nibs);
    if ((lid & 7) == 0) {
        int wslot = wid * 4 + (lid >> 3);
        zg[wslot] = wg;
        zs[wslot] = ws;
    }
    __syncthreads();

    uint4 packv;
    unsigned* pk = (unsigned*)&packv;
    #pragma unroll
    for (int k = 0; k < 4; k++) {
        int dg = nz_d(zg, j4 + k);
        int ds = nz_d(zs, j4 + k);
        pk[k] = (unsigned)dg | ((unsigned)ds << 16);
    }
    *(uint4*)(g_pack + ((size_t)b * HH + row) * WW + j4) = packv;

    // Pointwise terms (fast-math CE; rel err ~1e-6, budget is 1e-3)
    float v0 = 0.f, v1 = 0.f, v2 = 0.f, v3 = 0.f;
    #pragma unroll
    for (int k = 0; k < 4; k++) {
        float labf = (lba[k] > 0) ? 1.0f : 0.0f;
        float mx   = fmaxf(p0a[k], p1a[k]);
        float lse  = mx + __logf(__expf(p0a[k] - mx) + __expf(p1a[k] - mx));
        float picked = (lba[k] > 0) ? p1a[k] : p0a[k];
        v0 += p1a[k] * labf;
        v1 += p1a[k] * p1a[k];
        v2 += labf;
        v3 += lse - picked;
    }

    #pragma unroll
    for (int off = 16; off > 0; off >>= 1) {
        v0 += __shfl_down_sync(0xFFFFFFFFu, v0, off);
        v1 += __shfl_down_sync(0xFFFFFFFFu, v1, off);
        v2 += __shfl_down_sync(0xFFFFFFFFu, v2, off);
        v3 += __shfl_down_sync(0xFFFFFFFFu, v3, off);
    }
    __shared__ float sb[4][4];
    if (lid == 0) { sb[wid][0] = v0; sb[wid][1] = v1; sb[wid][2] = v2; sb[wid][3] = v3; }
    __syncthreads();
    if (t < 4) {
        double s = 0.0;
        #pragma unroll
        for (int w = 0; w < 4; w++) s += (double)sb[w][t];
        g_part[(b * HH + row) * 4 + t] = s;
    }
}

// Pass 2: column-direction EDT, 4 pixels/thread via uint4 window loads
// (r<=2 unconditional, exact serial tail for the rare rest); HD partial
// sum; last-block finalize.
__global__ void __launch_bounds__(512) pass2_k(const float* __restrict__ outputs,
                                               const int* __restrict__ label,
                                               float* __restrict__ out) {
    int b  = blockIdx.z;
    int i  = blockIdx.y * 16 + threadIdx.y;          // row
    int j4 = (blockIdx.x * 32 + threadIdx.x) * 4;    // first of 4 columns

    const unsigned* __restrict__ P = g_pack + (size_t)b * HH * WW;

    // HD-term inputs issued early to overlap with window loads
    size_t base1 = ((size_t)(b * 2 + 1) * HH + i) * WW + j4;
    float4 p1v = *(const float4*)(outputs + base1);
    int4   lbv = *(const int4*)(label + base1);

    uint4 c0 = *(const uint4*)(P + i * WW + j4);
    int iu1 = max(i - 1, 0), id1 = min(i + 1, HH - 1);
    int iu2 = max(i - 2, 0), id2 = min(i + 2, HH - 1);
    uint4 cu1 = *(const uint4*)(P + iu1 * WW + j4);
    uint4 cd1 = *(const uint4*)(P + id1 * WW + j4);
    uint4 cu2 = *(const uint4*)(P + iu2 * WW + j4);
    uint4 cd2 = *(const uint4*)(P + id2 * WW + j4);

    const unsigned* a0 = (const unsigned*)&c0;
    const unsigned* a1 = (const unsigned*)&cu1;
    const unsigned* a2 = (const unsigned*)&cd1;
    const unsigned* a3 = (const unsigned*)&cu2;
    const unsigned* a4 = (const unsigned*)&cd2;

    int bestG[4], bestS[4];
    bool anyTail = false;
    #pragma unroll
    for (int k = 0; k < 4; k++) {
        int g = (int)(a0[k] & 0xFFFFu); g = g * g;
        int s = (int)(a0[k] >> 16);     s = s * s;
        int v;
        v = (int)(a1[k] & 0xFFFFu); g = min(g, v * v + 1);
        v = (int)(a1[k] >> 16);     s = min(s, v * v + 1);
        v = (int)(a2[k] & 0xFFFFu); g = min(g, v * v + 1);
        v = (int)(a2[k] >> 16);     s = min(s, v * v + 1);
        v = (int)(a3[k] & 0xFFFFu); g = min(g, v * v + 4);
        v = (int)(a3[k] >> 16);     s = min(s, v * v + 4);
        v = (int)(a4[k] & 0xFFFFu); g = min(g, v * v + 4);
        v = (int)(a4[k] >> 16);     s = min(s, v * v + 4);
        bestG[k] = g; bestS[k] = s;
        anyTail |= (g > 9) | (s > 9);
    }

    if (anyTail) {
        #pragma unroll
        for (int k = 0; k < 4; k++) {
            if (bestG[k] <= 9 && bestS[k] <= 9) continue;
            int j = j4 + k;
            for (int r = 3; r < HH; r++) {
                int r2 = r * r;
                if (r2 >= bestG[k] && r2 >= bestS[k]) break;
                if (i - r >= 0) {
                    unsigned cc = P[(i - r) * WW + j];
                    int vg = (int)(cc & 0xFFFFu);
                    int vs = (int)(cc >> 16);
                    bestG[k] = min(bestG[k], vg * vg + r2);
                    bestS[k] = min(bestS[k], vs * vs + r2);
                }
                if (i + r < HH) {
                    unsigned cc = P[(i + r) * WW + j];
                    int vg = (int)(cc & 0xFFFFu);
                    int vs = (int)(cc >> 16);
                    bestG[k] = min(bestG[k], vg * vg + r2);
                    bestS[k] = min(bestS[k], vs * vs + r2);
                }
            }
        }
    }

    float p1a[4] = {p1v.x, p1v.y, p1v.z, p1v.w};
    int   lba[4] = {lbv.x, lbv.y, lbv.z, lbv.w};
    float hd = 0.f;
    #pragma unroll
    for (int k = 0; k < 4; k++) {
        float d2g = (bestG[k] >= SENT2) ? INF_F : (float)bestG[k];
        float d2s = (bestS[k] >= SENT2) ? INF_F : (float)bestS[k];
        float labf = (lba[k] > 0) ? 1.0f : 0.0f;
        float dlt  = p1a[k] - labf;
        hd += (dlt * dlt) * (d2s + d2g);
    }

    #pragma unroll
    for (int off = 16; off > 0; off >>= 1)
        hd += __shfl_down_sync(0xFFFFFFFFu, hd, off);

    __shared__ double sbh[16];
    int tid = threadIdx.y * 32 + threadIdx.x;
    int wid = tid >> 5, lid = tid & 31;
    if (lid == 0) sbh[wid] = (double)hd;
    __syncthreads();

    int bid = (blockIdx.z * gridDim.y + blockIdx.y) * gridDim.x + blockIdx.x;
    if (tid < 16) {
        double s = sbh[tid];
        #pragma unroll
        for (int off = 8; off > 0; off >>= 1)
            s += __shfl_down_sync(0x0000FFFFu, s, off);
        if (tid == 0) g_hd[bid] = s;
    }

    // ── last-block finalize ──
    __shared__ bool isLast;
    if (tid == 0) {
        __threadfence();
        unsigned cnum = atomicAdd(&g_count, 1u);
        isLast = (cnum == NBLK2 - 1);
    }
    __syncthreads();
    if (!isLast) return;
    __threadfence();

    double s0 = 0.0, s1 = 0.0, s2 = 0.0, s3 = 0.0, sh = 0.0;
    for (int k = tid; k < NBLK1; k += 512) {
        s0 += g_part[k * 4 + 0];
        s1 += g_part[k * 4 + 1];
        s2 += g_part[k * 4 + 2];
        s3 += g_part[k * 4 + 3];
    }
    for (int k = tid; k < NBLK2; k += 512) sh += g_hd[k];

    #pragma unroll
    for (int off = 16; off > 0; off >>= 1) {
        s0 += __shfl_down_sync(0xFFFFFFFFu, s0, off);
        s1 += __shfl_down_sync(0xFFFFFFFFu, s1, off);
        s2 += __shfl_down_sync(0xFFFFFFFFu, s2, off);
        s3 += __shfl_down_sync(0xFFFFFFFFu, s3, off);
        sh += __shfl_down_sync(0xFFFFFFFFu, sh, off);
    }
    __shared__ double fb[16][5];
    if (lid == 0) { fb[wid][0]=s0; fb[wid][1]=s1; fb[wid][2]=s2; fb[wid][3]=s3; fb[wid][4]=sh; }
    __syncthreads();
    if (tid == 0) {
        double a0d=0, a1d=0, a2d=0, a3d=0, ahd=0;
        #pragma unroll
        for (int w = 0; w < 16; w++) {
            a0d += fb[w][0]; a1d += fb[w][1]; a2d += fb[w][2]; a3d += fb[w][3]; ahd += fb[w][4];
        }
        double N    = (double)NPIX;
        double hdm  = ahd / N;
        double dice = 1.0 - (2.0 * a0d + 1e-6) / (a1d + a2d + 1e-6);
        double ce   = a3d / N;
        // LAM = 1.0, ALPHA = 0.5 -> loss = (ce + dice) + 0.5 * hd
        out[0] = (float)((ce + dice) + 0.5 * hdm);
        g_count = 0;   // reset for next graph replay
    }
}

extern "C" void kernel_launch(void* const* d_in, const int* in_sizes, int n_in,
                              void* d_out, int out_size) {
    const float* outputs = (const float*)d_in[0];
    const int*   label   = (const int*)d_in[1];
    float*       out     = (float*)d_out;

    dim3 g1(HH, BB);
    pass1_k<<<g1, 128>>>(outputs, label);

    dim3 b2(32, 16);
    dim3 g2(4, 32, BB);
    pass2_k<<<g2, b2>>>(outputs, label, out);
}